// round 5
// baseline (speedup 1.0000x reference)
#include <cuda_runtime.h>
#include <math.h>

#define BB 2
#define HH 8
#define NN 512
#define DD 64
#define TT 512      // DFT input (nonzero) length
#define MM 512      // DFT output frequencies kept
#define CC 2048     // GEMM columns: 2 tensors * 16 bh * 64 j

#define X_ELEMS   (BB*NN*512)   // 524288
#define W_ELEMS   (512*512)     // 262144
#define OUT_F2    (BB*HH*NN*DD) // 524288 complex outputs

typedef unsigned long long ull;

// Packed fp32x2 FMA (Blackwell): d = a*b + d per 32-bit lane.
#define FMA2(d, a, b) asm("fma.rn.f32x2 %0, %1, %2, %0;" : "+l"(d) : "l"(a), "l"(b))

__device__ __forceinline__ float2 u2f(ull v) {
    float2 f;
    asm("mov.b64 {%0, %1}, %2;" : "=f"(f.x), "=f"(f.y) : "l"(v));
    return f;
}

__device__ __forceinline__ int iclamp(int i, int n) { return i < n ? (i < 0 ? 0 : i) : n - 1; }

// ---------------- scratch ----------------
__device__ float g_kraw[BB*NN*512];
__device__ float g_v   [BB*NN*512];
__device__ float g_part[128];
__device__ float g_Ac[256*TT];        // cos rows m=0..255 (pairing covers 257..511)
__device__ float g_As[256*TT];        // -sin rows m=0..255
__device__ float g_inb[TT*CC];
__device__ float g_re [MM*CC];
__device__ float g_im [MM*CC];

// ---------------- K1: merged projections k = x@Wk, v = x@Wv (f32x2: (k,v) packed) ------
// 256 threads, tile 64 rows x 64 cols; tx=tidx&7 -> 8 cols, ty=tidx>>3 -> 2 rows.
__global__ void k_proj(const float* __restrict__ X,
                       const float* __restrict__ Wkm,
                       const float* __restrict__ Wvm) {
    const int tidx = threadIdx.x;
    const int tx = tidx & 7, ty = tidx >> 3;
    const int n0 = blockIdx.x * 64;
    const int m0 = blockIdx.y * 64;

    __shared__ float sA2 [16][132];   // x, duplicated pairs: [t][2m]=(a,a)
    __shared__ float sBkv[16][132];   // interleaved: [t][2c]=(wk,wv)
    __shared__ float sred[256];

    ull acc[2][8];
#pragma unroll
    for (int r = 0; r < 2; r++)
#pragma unroll
        for (int c = 0; c < 8; c++) acc[r][c] = 0ull;

    for (int k0 = 0; k0 < 512; k0 += 16) {
        // load A (x tile) with duplication
        {
            int t_off = tidx & 15, mb = tidx >> 4;
#pragma unroll
            for (int i = 0; i < 4; i++) {
                int m = mb + i*16;
                float v = X[iclamp((m0 + m)*512 + k0 + t_off, X_ELEMS)];
                float2 d; d.x = v; d.y = v;
                *(float2*)&sA2[t_off][2*m] = d;
            }
        }
        // load Wk/Wv interleaved
        {
            int c = tidx & 63, tb = tidx >> 6;
#pragma unroll
            for (int i = 0; i < 4; i++) {
                int t = tb + i*4;
                int widx = iclamp((k0 + t)*512 + n0 + c, W_ELEMS);
                float2 d; d.x = Wkm[widx]; d.y = Wvm[widx];
                *(float2*)&sBkv[t][2*c] = d;
            }
        }
        __syncthreads();
#pragma unroll
        for (int kk = 0; kk < 16; kk++) {
            ull a0 = *(const ull*)&sA2[kk][(ty*2 + 0)*2];
            ull a1 = *(const ull*)&sA2[kk][(ty*2 + 1)*2];
            ulonglong2 b01 = *(const ulonglong2*)&sBkv[kk][tx*16];
            ulonglong2 b23 = *(const ulonglong2*)&sBkv[kk][tx*16 + 4];
            ulonglong2 b45 = *(const ulonglong2*)&sBkv[kk][tx*16 + 8];
            ulonglong2 b67 = *(const ulonglong2*)&sBkv[kk][tx*16 + 12];
            FMA2(acc[0][0], a0, b01.x); FMA2(acc[0][1], a0, b01.y);
            FMA2(acc[0][2], a0, b23.x); FMA2(acc[0][3], a0, b23.y);
            FMA2(acc[0][4], a0, b45.x); FMA2(acc[0][5], a0, b45.y);
            FMA2(acc[0][6], a0, b67.x); FMA2(acc[0][7], a0, b67.y);
            FMA2(acc[1][0], a1, b01.x); FMA2(acc[1][1], a1, b01.y);
            FMA2(acc[1][2], a1, b23.x); FMA2(acc[1][3], a1, b23.y);
            FMA2(acc[1][4], a1, b45.x); FMA2(acc[1][5], a1, b45.y);
            FMA2(acc[1][6], a1, b67.x); FMA2(acc[1][7], a1, b67.y);
        }
        __syncthreads();
    }

    float nsum = 0.f;
#pragma unroll
    for (int r = 0; r < 2; r++)
#pragma unroll
        for (int c = 0; c < 8; c++) {
            float2 kv = u2f(acc[r][c]);
            int o = (m0 + ty*2 + r)*512 + n0 + tx*8 + c;
            g_kraw[o] = kv.x;
            g_v[o]    = kv.y;
            nsum += kv.x * kv.x;
        }
    // deterministic block reduction of k-norm partial
    sred[tidx] = nsum; __syncthreads();
    for (int o = 128; o > 0; o >>= 1) {
        if (tidx < o) sred[tidx] += sred[tidx + o];
        __syncthreads();
    }
    if (tidx == 0) g_part[blockIdx.y*8 + blockIdx.x] = sred[0];
}

// ---------------- K3: rnorm + elu + per-head sums + pack B + build DFT table ----------
__global__ void k_prep() {
    int bt = blockIdx.x;           // b*512 + t
    int b  = bt >> 9;
    int t  = bt & 511;
    int tid = threadIdx.x;         // 0..511 = h*64 + j

    __shared__ float rs[128];
    __shared__ float sh_rn;
    if (tid < 128) rs[tid] = g_part[tid];
    __syncthreads();
    if (tid == 0) {
        float s = 0.f;
#pragma unroll 8
        for (int i = 0; i < 128; i++) s += rs[i];
        sh_rn = 1.0f / sqrtf(s);
    }
    // build DFT matrix row m=bt (blocks 0..255 only); independent of rnorm
    if (bt < 256) {
        int k = (bt * tid) & 1023;
        float sn, cn;
        sincospif((float)k * (1.0f / 512.0f), &sn, &cn);
        g_Ac[bt*TT + tid] = cn;
        g_As[bt*TT + tid] = -sn;
    }
    __syncthreads();
    float rn = sh_rn;

    float kv = g_kraw[bt*512 + tid] * rn;
    float ke = kv > 0.f ? kv : expm1f(kv);

    float s = ke;
#pragma unroll
    for (int o = 16; o > 0; o >>= 1) s += __shfl_down_sync(0xffffffffu, s, o);
    __shared__ float wsum[16];
    __shared__ float hsum[8];
    int warp = tid >> 5;
    if ((tid & 31) == 0) wsum[warp] = s;
    __syncthreads();
    if (tid < 8) hsum[tid] = wsum[2*tid] + wsum[2*tid + 1];
    __syncthreads();

    int h = tid >> 6;
    float u = hsum[h] * g_v[bt*512 + tid];
    g_inb[t*CC + b*512 + tid]        = u;    // numerator tensor
    g_inb[t*CC + 1024 + b*512 + tid] = ke;   // denominator tensor
}

// ---------------- K4: paired dual-DFT GEMM with f32x2 (adjacent cols packed) ----------
// 256 threads, tile 64 m-rows x 64 cols; tx=tidx&7 -> 8 cols (4 pairs), ty=tidx>>3 -> 2 rows.
// Parity split over t gives rows m and 512-m from the same MACs.
__global__ void k_dft() {
    const int tidx = threadIdx.x;
    const int tx = tidx & 7, ty = tidx >> 3;
    const int n0 = blockIdx.x * 64;        // col
    const int m0 = blockIdx.y * 64;        // freq row base (m in 0..255)

    __shared__ float sAc2[16][132];   // cos, duplicated pairs
    __shared__ float sAs2[16][132];   // -sin, duplicated pairs
    __shared__ float sB  [16][64];

    ull aRe[2][2][4], aIm[2][2][4];   // [parity][row][colpair]
#pragma unroll
    for (int p = 0; p < 2; p++)
#pragma unroll
        for (int r = 0; r < 2; r++)
#pragma unroll
            for (int c = 0; c < 4; c++) { aRe[p][r][c] = 0ull; aIm[p][r][c] = 0ull; }

    for (int k0 = 0; k0 < 512; k0 += 16) {
        {
            int t_off = tidx & 15, mb = tidx >> 4;
#pragma unroll
            for (int i = 0; i < 4; i++) {
                int m = mb + i*16;
                int idx = (m0 + m)*TT + k0 + t_off;
                float c = g_Ac[idx], s = g_As[idx];
                float2 dc; dc.x = c; dc.y = c;
                float2 ds; ds.x = s; ds.y = s;
                *(float2*)&sAc2[t_off][2*m] = dc;
                *(float2*)&sAs2[t_off][2*m] = ds;
            }
        }
        {
            int c = tidx & 63, tb = tidx >> 6;
#pragma unroll
            for (int i = 0; i < 4; i++) {
                int t = tb + i*4;
                sB[t][c] = g_inb[(k0 + t)*CC + n0 + c];
            }
        }
        __syncthreads();
#pragma unroll
        for (int kk = 0; kk < 16; kk++) {
            const int p = kk & 1;
            ull c0 = *(const ull*)&sAc2[kk][(ty*2 + 0)*2];
            ull c1 = *(const ull*)&sAc2[kk][(ty*2 + 1)*2];
            ull s0 = *(const ull*)&sAs2[kk][(ty*2 + 0)*2];
            ull s1 = *(const ull*)&sAs2[kk][(ty*2 + 1)*2];
            ulonglong2 bq0 = *(const ulonglong2*)&sB[kk][tx*8];
            ulonglong2 bq1 = *(const ulonglong2*)&sB[kk][tx*8 + 4];
            FMA2(aRe[p][0][0], c0, bq0.x); FMA2(aRe[p][0][1], c0, bq0.y);
            FMA2(aRe[p][0][2], c0, bq1.x); FMA2(aRe[p][0][3], c0, bq1.y);
            FMA2(aRe[p][1][0], c1, bq0.x); FMA2(aRe[p][1][1], c1, bq0.y);
            FMA2(aRe[p][1][2], c1, bq1.x); FMA2(aRe[p][1][3], c1, bq1.y);
            FMA2(aIm[p][0][0], s0, bq0.x); FMA2(aIm[p][0][1], s0, bq0.y);
            FMA2(aIm[p][0][2], s0, bq1.x); FMA2(aIm[p][0][3], s0, bq1.y);
            FMA2(aIm[p][1][0], s1, bq0.x); FMA2(aIm[p][1][1], s1, bq0.y);
            FMA2(aIm[p][1][2], s1, bq1.x); FMA2(aIm[p][1][3], s1, bq1.y);
        }
        __syncthreads();
    }

#pragma unroll
    for (int r = 0; r < 2; r++) {
        int mp = m0 + ty*2 + r;                   // 0..255
        int mq = 512 - mp;                        // 257..512
#pragma unroll
        for (int cp = 0; cp < 4; cp++) {
            int col = n0 + tx*8 + cp*2;
            float2 reE = u2f(aRe[0][r][cp]), reO = u2f(aRe[1][r][cp]);
            float2 imE = u2f(aIm[0][r][cp]), imO = u2f(aIm[1][r][cp]);
            int o1 = mp*CC + col;
            g_re[o1]   = reE.x + reO.x;  g_re[o1+1] = reE.y + reO.y;
            g_im[o1]   = imE.x + imO.x;  g_im[o1+1] = imE.y + imO.y;
            if (mq < MM) {
                int o2 = mq*CC + col;
                g_re[o2]   = reE.x - reO.x;  g_re[o2+1] = reE.y - reO.y;
                g_im[o2]   = imO.x - imE.x;  g_im[o2+1] = imO.y - imE.y;
            }
        }
    }
}

// ---------------- K4b: row m=256 (cos/sin are 0/±1 patterns) ----------------
__global__ void k_dft256() {
    int c = blockIdx.x * 256 + threadIdx.x;   // 0..2047
    float re = 0.f, im = 0.f;
#pragma unroll 4
    for (int t = 0; t < 512; t += 4) {
        re += g_inb[t*CC + c]     - g_inb[(t+2)*CC + c];
        im += g_inb[(t+3)*CC + c] - g_inb[(t+1)*CC + c];
    }
    g_re[256*CC + c] = re;
    g_im[256*CC + c] = im;
}

// ---------------- K5: (b,h) 2x8 DFT mix + complex division ----------------
__global__ void k_mix(float* __restrict__ out, int cap_floats, int mode) {
    int m = blockIdx.x;      // 0..511
    int j = threadIdx.x;     // 0..63

    float pur[16], pui[16], pkr[16], pki[16];
#pragma unroll
    for (int bh = 0; bh < 16; bh++) {
        int cu = m*CC + bh*64 + j;
        pur[bh] = g_re[cu];        pui[bh] = g_im[cu];
        pkr[bh] = g_re[cu + 1024]; pki[bh] = g_im[cu + 1024];
    }

    const float R2 = 0.70710678118654752f;
    const float w8r[8] = {1.f,  R2, 0.f, -R2, -1.f, -R2, 0.f,  R2};
    const float w8i[8] = {0.f, -R2, -1.f, -R2, 0.f,  R2, 1.f,  R2};

#pragma unroll
    for (int h0 = 0; h0 < 8; h0++) {
        float eur=0,eui=0,our_=0,oui=0, ekr=0,eki=0,okr=0,oki=0;
#pragma unroll
        for (int hp = 0; hp < 8; hp++) {
            int kq = (h0 * hp) & 7;
            float wr = w8r[kq], wi = w8i[kq];
            eur  += wr*pur[hp]   - wi*pui[hp];
            eui  += wr*pui[hp]   + wi*pur[hp];
            our_ += wr*pur[8+hp] - wi*pui[8+hp];
            oui  += wr*pui[8+hp] + wi*pur[8+hp];
            ekr  += wr*pkr[hp]   - wi*pki[hp];
            eki  += wr*pki[hp]   + wi*pkr[hp];
            okr  += wr*pkr[8+hp] - wi*pki[8+hp];
            oki  += wr*pki[8+hp] + wi*pkr[8+hp];
        }
#pragma unroll
        for (int b0 = 0; b0 < 2; b0++) {
            float sg = b0 ? -1.f : 1.f;
            float nr = eur + sg*our_, ni = eui + sg*oui;
            float dr = ekr + sg*okr,  di = eki + sg*oki;
            float inv = 1.0f / (dr*dr + di*di);
            float orr = (nr*dr + ni*di) * inv;
            float oii = (ni*dr - nr*di) * inv;
            int idx = (((b0*8 + h0)*512 + m)*64) + j;
            if (mode) {
                int f = 2*idx;
                if (f + 1 < cap_floats) { out[f] = orr; out[f+1] = oii; }
            } else {
                if (idx < cap_floats) out[idx] = orr;
            }
        }
    }
}

// ---------------- launch ----------------
extern "C" void kernel_launch(void* const* d_in, const int* in_sizes, int n_in,
                              void* d_out, int out_size) {
    const float* x = nullptr;
    const float* Ws[3] = {nullptr, nullptr, nullptr};

    int xi = -1; long long xmax = -1;
    for (int i = 0; i < n_in; i++)
        if ((long long)in_sizes[i] > xmax) { xmax = in_sizes[i]; xi = i; }
    if (xi >= 0) x = (const float*)d_in[xi];

    int wcount = 0;
    for (int i = 0; i < n_in && wcount < 3; i++) {
        if (i == xi) continue;
        int same = 0;
        for (int k2 = 0; k2 < n_in; k2++)
            if (k2 != xi && in_sizes[k2] == in_sizes[i]) same++;
        if (same == 3) Ws[wcount++] = (const float*)d_in[i];
    }
    if ((!Ws[0] || !Ws[1] || !Ws[2]) && n_in >= 4) {
        x = (const float*)d_in[0];
        Ws[0] = (const float*)d_in[1];
        Ws[1] = (const float*)d_in[2];
        Ws[2] = (const float*)d_in[3];
    }
    const float* Wk = Ws[1];
    const float* Wv = Ws[2];
    if (!x || !Wk || !Wv || !d_out || out_size <= 0) return;

    int mode, cap_floats;
    if (out_size >= 2*OUT_F2) { mode = 1; cap_floats = 2*OUT_F2; }
    else                      { mode = 0; cap_floats = out_size < OUT_F2 ? out_size : OUT_F2; }

    k_proj<<<dim3(8, 16), 256>>>(x, Wk, Wv);
    k_prep<<<1024, 512>>>();
    k_dft<<<dim3(32, 4), 256>>>();
    k_dft256<<<8, 256>>>();
    k_mix<<<512, 64>>>((float*)d_out, cap_floats, mode);
}

// round 6
// speedup vs baseline: 2.0441x; 2.0441x over previous
#include <cuda_runtime.h>
#include <math.h>

#define BB 2
#define HH 8
#define NN 512
#define DD 64
#define TT 512      // DFT input (nonzero) length
#define MM 512      // DFT output frequencies kept
#define CC 2048     // GEMM columns: 2 tensors * 16 bh * 64 j

#define X_ELEMS   (BB*NN*512)   // 524288
#define W_ELEMS   (512*512)     // 262144
#define OUT_F2    (BB*HH*NN*DD) // 524288 complex outputs

__device__ __forceinline__ int iclamp(int i, int n) { return i < n ? (i < 0 ? 0 : i) : n - 1; }

// ---------------- scratch ----------------
__device__ float g_kraw[BB*NN*512];
__device__ float g_v   [BB*NN*512];
__device__ float g_part[128];
__device__ float g_Ac[256*TT];        // cos rows m=0..255 (pairing covers 257..511)
__device__ float g_As[256*TT];        // -sin rows m=0..255
__device__ float g_inb[TT*CC];
__device__ float g_re [MM*CC];
__device__ float g_im [MM*CC];

// ---------------- K1: merged projections k = x@Wk, v = x@Wv (scalar FFMA, round-4) ----
__global__ void k_proj(const float* __restrict__ X,
                       const float* __restrict__ Wkm,
                       const float* __restrict__ Wvm) {
    const int tidx = threadIdx.x;          // 256 threads
    const int tx = tidx & 15, ty = tidx >> 4;
    const int n0 = blockIdx.x * 64;
    const int m0 = blockIdx.y * 64;

    __shared__ float sA [16][65];
    __shared__ float sBk[16][64];
    __shared__ float sBv[16][64];
    __shared__ float sred[256];
    float ack[4][4] = {};
    float acv[4][4] = {};

    for (int k0 = 0; k0 < 512; k0 += 16) {
        int ak = tidx & 15, am = tidx >> 4;
#pragma unroll
        for (int i = 0; i < 4; i++)
            sA[ak][am + i*16] = X[iclamp((m0 + am + i*16)*512 + k0 + ak, X_ELEMS)];
        int bn = tidx & 63, bk = tidx >> 6;
#pragma unroll
        for (int i = 0; i < 4; i++) {
            int widx = iclamp((k0 + bk + i*4)*512 + n0 + bn, W_ELEMS);
            sBk[bk + i*4][bn] = Wkm[widx];
            sBv[bk + i*4][bn] = Wvm[widx];
        }
        __syncthreads();
#pragma unroll
        for (int kk = 0; kk < 16; kk++) {
            float a4[4], bk4[4], bv4[4];
#pragma unroll
            for (int r = 0; r < 4; r++) a4[r] = sA[kk][ty + 16*r];
#pragma unroll
            for (int c = 0; c < 4; c++) { bk4[c] = sBk[kk][tx + 16*c]; bv4[c] = sBv[kk][tx + 16*c]; }
#pragma unroll
            for (int r = 0; r < 4; r++)
#pragma unroll
                for (int c = 0; c < 4; c++) {
                    ack[r][c] += a4[r] * bk4[c];
                    acv[r][c] += a4[r] * bv4[c];
                }
        }
        __syncthreads();
    }

    float nsum = 0.f;
#pragma unroll
    for (int r = 0; r < 4; r++)
#pragma unroll
        for (int c = 0; c < 4; c++) {
            int o = (m0 + ty + 16*r)*512 + n0 + tx + 16*c;
            g_kraw[o] = ack[r][c];
            g_v[o]    = acv[r][c];
            nsum += ack[r][c] * ack[r][c];
        }
    // deterministic block reduction of the k-norm partial
    sred[tidx] = nsum; __syncthreads();
    for (int o = 128; o > 0; o >>= 1) {
        if (tidx < o) sred[tidx] += sred[tidx + o];
        __syncthreads();
    }
    if (tidx == 0) g_part[blockIdx.y*8 + blockIdx.x] = sred[0];
}

// ---------------- K3: rnorm + elu + per-head sums + pack B + build DFT table ----------
__global__ void k_prep() {
    int bt = blockIdx.x;           // b*512 + t
    int b  = bt >> 9;
    int t  = bt & 511;
    int tid = threadIdx.x;         // 0..511 = h*64 + j

    __shared__ float rs[128];
    __shared__ float sh_rn;
    if (tid < 128) rs[tid] = g_part[tid];
    __syncthreads();
    if (tid == 0) {
        float s = 0.f;
#pragma unroll 8
        for (int i = 0; i < 128; i++) s += rs[i];
        sh_rn = 1.0f / sqrtf(s);
    }
    // build DFT matrix row m=bt (blocks 0..255 only); independent of rnorm
    if (bt < 256) {
        int k = (bt * tid) & 1023;
        float sn, cn;
        sincospif((float)k * (1.0f / 512.0f), &sn, &cn);
        g_Ac[bt*TT + tid] = cn;
        g_As[bt*TT + tid] = -sn;
    }
    __syncthreads();
    float rn = sh_rn;

    float kv = g_kraw[bt*512 + tid] * rn;
    float ke = kv > 0.f ? kv : expm1f(kv);

    float s = ke;
#pragma unroll
    for (int o = 16; o > 0; o >>= 1) s += __shfl_down_sync(0xffffffffu, s, o);
    __shared__ float wsum[16];
    __shared__ float hsum[8];
    int warp = tid >> 5;
    if ((tid & 31) == 0) wsum[warp] = s;
    __syncthreads();
    if (tid < 8) hsum[tid] = wsum[2*tid] + wsum[2*tid + 1];
    __syncthreads();

    int h = tid >> 6;
    float u = hsum[h] * g_v[bt*512 + tid];
    g_inb[t*CC + b*512 + tid]        = u;    // numerator tensor
    g_inb[t*CC + 1024 + b*512 + tid] = ke;   // denominator tensor
}

// ---------------- K4: paired dual-DFT GEMM (scalar FFMA, parity split; round-4) -------
__global__ void k_dft() {
    const int tidx = threadIdx.x;          // 256 threads
    const int tx = tidx & 15, ty = tidx >> 4;
    const int n0 = blockIdx.x * 64;        // col
    const int m0 = blockIdx.y * 64;        // freq row base (m in 0..255)

    __shared__ float sAc[16][65];
    __shared__ float sAs[16][65];
    __shared__ float sB [16][64];
    float are[4][4] = {}, aro[4][4] = {};  // Re accum, even/odd t
    float aie[4][4] = {}, aio[4][4] = {};  // Im accum, even/odd t

    for (int k0 = 0; k0 < 512; k0 += 16) {
        int ak = tidx & 15, am = tidx >> 4;
#pragma unroll
        for (int i = 0; i < 4; i++) {
            int idx = (m0 + am + i*16)*TT + k0 + ak;
            sAc[ak][am + i*16] = g_Ac[idx];
            sAs[ak][am + i*16] = g_As[idx];
        }
        int bn = tidx & 63, bk = tidx >> 6;
#pragma unroll
        for (int i = 0; i < 4; i++)
            sB[bk + i*4][bn] = g_inb[(k0 + bk + i*4)*CC + n0 + bn];
        __syncthreads();
#pragma unroll
        for (int kk = 0; kk < 16; kk++) {     // t = k0+kk; parity = kk&1
            float c4[4], s4[4], b4[4];
#pragma unroll
            for (int r = 0; r < 4; r++) {
                c4[r] = sAc[kk][ty + 16*r];
                s4[r] = sAs[kk][ty + 16*r];
            }
#pragma unroll
            for (int c = 0; c < 4; c++) b4[c] = sB[kk][tx + 16*c];
            if ((kk & 1) == 0) {
#pragma unroll
                for (int r = 0; r < 4; r++)
#pragma unroll
                    for (int c = 0; c < 4; c++) {
                        are[r][c] += c4[r] * b4[c];
                        aie[r][c] += s4[r] * b4[c];
                    }
            } else {
#pragma unroll
                for (int r = 0; r < 4; r++)
#pragma unroll
                    for (int c = 0; c < 4; c++) {
                        aro[r][c] += c4[r] * b4[c];
                        aio[r][c] += s4[r] * b4[c];
                    }
            }
        }
        __syncthreads();
    }
#pragma unroll
    for (int r = 0; r < 4; r++)
#pragma unroll
        for (int c = 0; c < 4; c++) {
            int mp  = m0 + ty + 16*r;                 // 0..255
            int col = n0 + tx + 16*c;
            int o1 = mp*CC + col;
            g_re[o1] = are[r][c] + aro[r][c];
            g_im[o1] = aie[r][c] + aio[r][c];
            int mq = 512 - mp;                        // 257..512
            if (mq < MM) {
                int o2 = mq*CC + col;
                g_re[o2] = are[r][c] - aro[r][c];
                g_im[o2] = aio[r][c] - aie[r][c];
            }
        }
}

// ---------------- K4b: row m=256, parallelized 8x over t + tree reduce ----------------
// cos pattern (1,0,-1,0), sin pattern -> im uses (t%4==3) - (t%4==1)
__global__ void k_dft256() {
    __shared__ float sre[8][33];
    __shared__ float sim[8][33];
    int ci = threadIdx.x & 31;            // column within block
    int q  = threadIdx.x >> 5;            // t-chunk 0..7
    int c  = blockIdx.x * 32 + ci;        // 0..2047
    int t0 = q * 64;
    float re = 0.f, im = 0.f;
#pragma unroll 16
    for (int t = t0; t < t0 + 64; t += 4) {
        re += g_inb[t*CC + c]     - g_inb[(t+2)*CC + c];
        im += g_inb[(t+3)*CC + c] - g_inb[(t+1)*CC + c];
    }
    sre[q][ci] = re; sim[q][ci] = im;
    __syncthreads();
    if (threadIdx.x < 32) {
        float r = 0.f, i2 = 0.f;
#pragma unroll
        for (int qq = 0; qq < 8; qq++) { r += sre[qq][ci]; i2 += sim[qq][ci]; }
        g_re[256*CC + c] = r;
        g_im[256*CC + c] = i2;
    }
}

// ---------------- K5: (b,h) 2x8 DFT mix + complex division ----------------
__global__ void k_mix(float* __restrict__ out, int cap_floats, int mode) {
    int m = blockIdx.x;      // 0..511
    int j = threadIdx.x;     // 0..63

    float pur[16], pui[16], pkr[16], pki[16];
#pragma unroll
    for (int bh = 0; bh < 16; bh++) {
        int cu = m*CC + bh*64 + j;
        pur[bh] = g_re[cu];        pui[bh] = g_im[cu];
        pkr[bh] = g_re[cu + 1024]; pki[bh] = g_im[cu + 1024];
    }

    const float R2 = 0.70710678118654752f;
    const float w8r[8] = {1.f,  R2, 0.f, -R2, -1.f, -R2, 0.f,  R2};
    const float w8i[8] = {0.f, -R2, -1.f, -R2, 0.f,  R2, 1.f,  R2};

#pragma unroll
    for (int h0 = 0; h0 < 8; h0++) {
        float eur=0,eui=0,our_=0,oui=0, ekr=0,eki=0,okr=0,oki=0;
#pragma unroll
        for (int hp = 0; hp < 8; hp++) {
            int kq = (h0 * hp) & 7;
            float wr = w8r[kq], wi = w8i[kq];
            eur  += wr*pur[hp]   - wi*pui[hp];
            eui  += wr*pui[hp]   + wi*pur[hp];
            our_ += wr*pur[8+hp] - wi*pui[8+hp];
            oui  += wr*pui[8+hp] + wi*pur[8+hp];
            ekr  += wr*pkr[hp]   - wi*pki[hp];
            eki  += wr*pki[hp]   + wi*pkr[hp];
            okr  += wr*pkr[8+hp] - wi*pki[8+hp];
            oki  += wr*pki[8+hp] + wi*pkr[8+hp];
        }
#pragma unroll
        for (int b0 = 0; b0 < 2; b0++) {
            float sg = b0 ? -1.f : 1.f;
            float nr = eur + sg*our_, ni = eui + sg*oui;
            float dr = ekr + sg*okr,  di = eki + sg*oki;
            float inv = 1.0f / (dr*dr + di*di);
            float orr = (nr*dr + ni*di) * inv;
            float oii = (ni*dr - nr*di) * inv;
            int idx = (((b0*8 + h0)*512 + m)*64) + j;
            if (mode) {
                int f = 2*idx;
                if (f + 1 < cap_floats) { out[f] = orr; out[f+1] = oii; }
            } else {
                if (idx < cap_floats) out[idx] = orr;
            }
        }
    }
}

// ---------------- launch ----------------
extern "C" void kernel_launch(void* const* d_in, const int* in_sizes, int n_in,
                              void* d_out, int out_size) {
    const float* x = nullptr;
    const float* Ws[3] = {nullptr, nullptr, nullptr};

    int xi = -1; long long xmax = -1;
    for (int i = 0; i < n_in; i++)
        if ((long long)in_sizes[i] > xmax) { xmax = in_sizes[i]; xi = i; }
    if (xi >= 0) x = (const float*)d_in[xi];

    int wcount = 0;
    for (int i = 0; i < n_in && wcount < 3; i++) {
        if (i == xi) continue;
        int same = 0;
        for (int k2 = 0; k2 < n_in; k2++)
            if (k2 != xi && in_sizes[k2] == in_sizes[i]) same++;
        if (same == 3) Ws[wcount++] = (const float*)d_in[i];
    }
    if ((!Ws[0] || !Ws[1] || !Ws[2]) && n_in >= 4) {
        x = (const float*)d_in[0];
        Ws[0] = (const float*)d_in[1];
        Ws[1] = (const float*)d_in[2];
        Ws[2] = (const float*)d_in[3];
    }
    const float* Wk = Ws[1];
    const float* Wv = Ws[2];
    if (!x || !Wk || !Wv || !d_out || out_size <= 0) return;

    int mode, cap_floats;
    if (out_size >= 2*OUT_F2) { mode = 1; cap_floats = 2*OUT_F2; }
    else                      { mode = 0; cap_floats = out_size < OUT_F2 ? out_size : OUT_F2; }

    k_proj<<<dim3(8, 16), 256>>>(x, Wk, Wv);
    k_prep<<<1024, 512>>>();
    k_dft<<<dim3(32, 4), 256>>>();
    k_dft256<<<64, 256>>>();
    k_mix<<<512, 64>>>((float*)d_out, cap_floats, mode);
}

// round 7
// speedup vs baseline: 2.3047x; 1.1275x over previous
#include <cuda_runtime.h>
#include <math.h>

#define BB 2
#define HH 8
#define NN 512
#define DD 64
#define TT 512      // DFT input (nonzero) length
#define MM 512      // DFT output frequencies kept
#define CC 2048     // GEMM columns: 2 tensors * 16 bh * 64 j

#define X_ELEMS   (BB*NN*512)   // 524288
#define W_ELEMS   (512*512)     // 262144
#define OUT_F2    (BB*HH*NN*DD) // 524288 complex outputs

__device__ __forceinline__ int iclamp(int i, int n) { return i < n ? (i < 0 ? 0 : i) : n - 1; }

// ---------------- scratch ----------------
__device__ float g_kraw[BB*NN*512];
__device__ float g_v   [BB*NN*512];
__device__ float g_part[128];
__device__ float g_Ac[256*TT];        // cos rows m=0..255
__device__ float g_As[256*TT];        // -sin rows m=0..255
__device__ float g_inb[TT*CC];
__device__ float g_re [MM*CC];
__device__ float g_im [MM*CC];

// ---------------- K1: merged projections k = x@Wk, v = x@Wv ----------------
__global__ void k_proj(const float* __restrict__ X,
                       const float* __restrict__ Wkm,
                       const float* __restrict__ Wvm) {
    const int tidx = threadIdx.x;          // 256 threads
    const int tx = tidx & 15, ty = tidx >> 4;
    const int n0 = blockIdx.x * 64;
    const int m0 = blockIdx.y * 64;

    __shared__ float sA [16][65];
    __shared__ float sBk[16][64];
    __shared__ float sBv[16][64];
    __shared__ float sred[256];
    float ack[4][4] = {};
    float acv[4][4] = {};

    for (int k0 = 0; k0 < 512; k0 += 16) {
        int ak = tidx & 15, am = tidx >> 4;
#pragma unroll
        for (int i = 0; i < 4; i++)
            sA[ak][am + i*16] = X[iclamp((m0 + am + i*16)*512 + k0 + ak, X_ELEMS)];
        int bn = tidx & 63, bk = tidx >> 6;
#pragma unroll
        for (int i = 0; i < 4; i++) {
            int widx = iclamp((k0 + bk + i*4)*512 + n0 + bn, W_ELEMS);
            sBk[bk + i*4][bn] = Wkm[widx];
            sBv[bk + i*4][bn] = Wvm[widx];
        }
        __syncthreads();
#pragma unroll
        for (int kk = 0; kk < 16; kk++) {
            float a4[4], bk4[4], bv4[4];
#pragma unroll
            for (int r = 0; r < 4; r++) a4[r] = sA[kk][ty + 16*r];
#pragma unroll
            for (int c = 0; c < 4; c++) { bk4[c] = sBk[kk][tx + 16*c]; bv4[c] = sBv[kk][tx + 16*c]; }
#pragma unroll
            for (int r = 0; r < 4; r++)
#pragma unroll
                for (int c = 0; c < 4; c++) {
                    ack[r][c] += a4[r] * bk4[c];
                    acv[r][c] += a4[r] * bv4[c];
                }
        }
        __syncthreads();
    }

    float nsum = 0.f;
#pragma unroll
    for (int r = 0; r < 4; r++)
#pragma unroll
        for (int c = 0; c < 4; c++) {
            int o = (m0 + ty + 16*r)*512 + n0 + tx + 16*c;
            g_kraw[o] = ack[r][c];
            g_v[o]    = acv[r][c];
            nsum += ack[r][c] * ack[r][c];
        }
    sred[tidx] = nsum; __syncthreads();
    for (int o = 128; o > 0; o >>= 1) {
        if (tidx < o) sred[tidx] += sred[tidx + o];
        __syncthreads();
    }
    if (tidx == 0) g_part[blockIdx.y*8 + blockIdx.x] = sred[0];
}

// ---------------- K3: rnorm + elu + per-head sums + pack B + build DFT table ----------
__global__ void k_prep() {
    int bt = blockIdx.x;           // b*512 + t
    int b  = bt >> 9;
    int t  = bt & 511;
    int tid = threadIdx.x;         // 0..511 = h*64 + j

    __shared__ float rs[128];
    __shared__ float sh_rn;
    if (tid < 128) rs[tid] = g_part[tid];
    __syncthreads();
    if (tid == 0) {
        float s = 0.f;
#pragma unroll 8
        for (int i = 0; i < 128; i++) s += rs[i];
        sh_rn = 1.0f / sqrtf(s);
    }
    if (bt < 256) {
        int k = (bt * tid) & 1023;
        float sn, cn;
        sincospif((float)k * (1.0f / 512.0f), &sn, &cn);
        g_Ac[bt*TT + tid] = cn;
        g_As[bt*TT + tid] = -sn;
    }
    __syncthreads();
    float rn = sh_rn;

    float kv = g_kraw[bt*512 + tid] * rn;
    float ke = kv > 0.f ? kv : expm1f(kv);

    float s = ke;
#pragma unroll
    for (int o = 16; o > 0; o >>= 1) s += __shfl_down_sync(0xffffffffu, s, o);
    __shared__ float wsum[16];
    __shared__ float hsum[8];
    int warp = tid >> 5;
    if ((tid & 31) == 0) wsum[warp] = s;
    __syncthreads();
    if (tid < 8) hsum[tid] = wsum[2*tid] + wsum[2*tid + 1];
    __syncthreads();

    int h = tid >> 6;
    float u = hsum[h] * g_v[bt*512 + tid];
    g_inb[t*CC + b*512 + tid]        = u;    // numerator tensor
    g_inb[t*CC + 1024 + b*512 + tid] = ke;   // denominator tensor
}

// ---------------- K4: quad-row DFT GEMM via mod-4 t-class split ----------------
// One MAC set for row m (m in 0..128) yields rows m, 512-m, 256-m, 256+m.
// C_p = sum_{t=p mod 4} cos*b ; S_p = sum sin*b  (note g_As stores -sin).
__global__ void k_dft() {
    const int tidx = threadIdx.x;          // 256 threads
    const int tx = tidx & 15;              // 16 col groups of 4
    const int ty = tidx >> 4;              // 16 row groups of 2
    const int n0 = blockIdx.x * 64;        // col base
    const int m0 = blockIdx.y * 32;        // row base: 0,32,64,96,128

    __shared__ float sAc[16][34];          // cos, [t][row] (32 rows)
    __shared__ float sAn[16][34];          // -sin
    __shared__ float sB [16][64];

    float C[4][2][4] = {};                 // [class][row][col] cos sums
    float Nn[4][2][4] = {};                // (-sin) sums; S_p = -Nn_p

    for (int k0 = 0; k0 < 512; k0 += 16) {
        {
            int t = tidx & 15, rowg = tidx >> 4;          // rows rowg, rowg+16
            int i0 = (m0 + rowg)*TT + k0 + t;
            int i1 = (m0 + rowg + 16)*TT + k0 + t;
            sAc[t][rowg]      = g_Ac[i0];
            sAn[t][rowg]      = g_As[i0];
            sAc[t][rowg + 16] = g_Ac[i1];
            sAn[t][rowg + 16] = g_As[i1];
        }
        {
            int c = tidx & 63, tb = tidx >> 6;
#pragma unroll
            for (int i = 0; i < 4; i++)
                sB[tb + i*4][c] = g_inb[(k0 + tb + i*4)*CC + n0 + c];
        }
        __syncthreads();
#pragma unroll
        for (int kk = 0; kk < 16; kk++) {
            const int p = kk & 3;                          // t class (k0 % 4 == 0)
            float2 c2 = *(const float2*)&sAc[kk][ty*2];
            float2 s2 = *(const float2*)&sAn[kk][ty*2];
            float4 b4 = *(const float4*)&sB[kk][tx*4];
            C[p][0][0]  += c2.x*b4.x; C[p][0][1]  += c2.x*b4.y;
            C[p][0][2]  += c2.x*b4.z; C[p][0][3]  += c2.x*b4.w;
            C[p][1][0]  += c2.y*b4.x; C[p][1][1]  += c2.y*b4.y;
            C[p][1][2]  += c2.y*b4.z; C[p][1][3]  += c2.y*b4.w;
            Nn[p][0][0] += s2.x*b4.x; Nn[p][0][1] += s2.x*b4.y;
            Nn[p][0][2] += s2.x*b4.z; Nn[p][0][3] += s2.x*b4.w;
            Nn[p][1][0] += s2.y*b4.x; Nn[p][1][1] += s2.y*b4.y;
            Nn[p][1][2] += s2.y*b4.z; Nn[p][1][3] += s2.y*b4.w;
        }
        __syncthreads();
    }

#pragma unroll
    for (int r = 0; r < 2; r++) {
        int mp = m0 + ty*2 + r;                // 0..159 (writes only for mp<=128)
#pragma unroll
        for (int cc = 0; cc < 4; cc++) {
            int col = n0 + tx*4 + cc;
            float c0 = C[0][r][cc], c1 = C[1][r][cc], c2v = C[2][r][cc], c3 = C[3][r][cc];
            // S_p = -Nn_p
            float s0 = -Nn[0][r][cc], s1 = -Nn[1][r][cc], s2v = -Nn[2][r][cc], s3 = -Nn[3][r][cc];
            float cE = c0 + c2v, cO = c1 + c3;
            float sE = s0 + s2v, sO = s1 + s3;
            float cD = c0 - c2v, cF = c1 - c3;
            float sD = s0 - s2v, sF = s1 - s3;

            if (mp <= 128) {                           // row m
                int o = mp*CC + col;
                g_re[o] = cE + cO;
                g_im[o] = -(sE + sO);
            }
            if (mp >= 1 && mp <= 127) {                // row 512-m
                int o = (512 - mp)*CC + col;
                g_re[o] = cE - cO;
                g_im[o] = sE - sO;
            }
            if (mp <= 127) {                           // row 256-m (incl. 256 at mp=0)
                int o = (256 - mp)*CC + col;
                g_re[o] = cD + sF;
                g_im[o] = sD - cF;
            }
            if (mp >= 1 && mp <= 128) {                // row 256+m
                int o = (256 + mp)*CC + col;
                g_re[o] = cD - sF;
                g_im[o] = -sD - cF;
            }
        }
    }
}

// ---------------- K5: (b,h) 2x8 DFT mix + complex division ----------------
__global__ void k_mix(float* __restrict__ out, int cap_floats, int mode) {
    int m = blockIdx.x;      // 0..511
    int j = threadIdx.x;     // 0..63

    float pur[16], pui[16], pkr[16], pki[16];
#pragma unroll
    for (int bh = 0; bh < 16; bh++) {
        int cu = m*CC + bh*64 + j;
        pur[bh] = g_re[cu];        pui[bh] = g_im[cu];
        pkr[bh] = g_re[cu + 1024]; pki[bh] = g_im[cu + 1024];
    }

    const float R2 = 0.70710678118654752f;
    const float w8r[8] = {1.f,  R2, 0.f, -R2, -1.f, -R2, 0.f,  R2};
    const float w8i[8] = {0.f, -R2, -1.f, -R2, 0.f,  R2, 1.f,  R2};

#pragma unroll
    for (int h0 = 0; h0 < 8; h0++) {
        float eur=0,eui=0,our_=0,oui=0, ekr=0,eki=0,okr=0,oki=0;
#pragma unroll
        for (int hp = 0; hp < 8; hp++) {
            int kq = (h0 * hp) & 7;
            float wr = w8r[kq], wi = w8i[kq];
            eur  += wr*pur[hp]   - wi*pui[hp];
            eui  += wr*pui[hp]   + wi*pur[hp];
            our_ += wr*pur[8+hp] - wi*pui[8+hp];
            oui  += wr*pui[8+hp] + wi*pur[8+hp];
            ekr  += wr*pkr[hp]   - wi*pki[hp];
            eki  += wr*pki[hp]   + wi*pkr[hp];
            okr  += wr*pkr[8+hp] - wi*pki[8+hp];
            oki  += wr*pki[8+hp] + wi*pkr[8+hp];
        }
#pragma unroll
        for (int b0 = 0; b0 < 2; b0++) {
            float sg = b0 ? -1.f : 1.f;
            float nr = eur + sg*our_, ni = eui + sg*oui;
            float dr = ekr + sg*okr,  di = eki + sg*oki;
            float inv = 1.0f / (dr*dr + di*di);
            float orr = (nr*dr + ni*di) * inv;
            float oii = (ni*dr - nr*di) * inv;
            int idx = (((b0*8 + h0)*512 + m)*64) + j;
            if (mode) {
                int f = 2*idx;
                if (f + 1 < cap_floats) { out[f] = orr; out[f+1] = oii; }
            } else {
                if (idx < cap_floats) out[idx] = orr;
            }
        }
    }
}

// ---------------- launch ----------------
extern "C" void kernel_launch(void* const* d_in, const int* in_sizes, int n_in,
                              void* d_out, int out_size) {
    const float* x = nullptr;
    const float* Ws[3] = {nullptr, nullptr, nullptr};

    int xi = -1; long long xmax = -1;
    for (int i = 0; i < n_in; i++)
        if ((long long)in_sizes[i] > xmax) { xmax = in_sizes[i]; xi = i; }
    if (xi >= 0) x = (const float*)d_in[xi];

    int wcount = 0;
    for (int i = 0; i < n_in && wcount < 3; i++) {
        if (i == xi) continue;
        int same = 0;
        for (int k2 = 0; k2 < n_in; k2++)
            if (k2 != xi && in_sizes[k2] == in_sizes[i]) same++;
        if (same == 3) Ws[wcount++] = (const float*)d_in[i];
    }
    if ((!Ws[0] || !Ws[1] || !Ws[2]) && n_in >= 4) {
        x = (const float*)d_in[0];
        Ws[0] = (const float*)d_in[1];
        Ws[1] = (const float*)d_in[2];
        Ws[2] = (const float*)d_in[3];
    }
    const float* Wk = Ws[1];
    const float* Wv = Ws[2];
    if (!x || !Wk || !Wv || !d_out || out_size <= 0) return;

    int mode, cap_floats;
    if (out_size >= 2*OUT_F2) { mode = 1; cap_floats = 2*OUT_F2; }
    else                      { mode = 0; cap_floats = out_size < OUT_F2 ? out_size : OUT_F2; }

    k_proj<<<dim3(8, 16), 256>>>(x, Wk, Wv);
    k_prep<<<1024, 512>>>();
    k_dft<<<dim3(32, 5), 256>>>();
    k_mix<<<512, 64>>>((float*)d_out, cap_floats, mode);
}

// round 9
// speedup vs baseline: 2.3990x; 1.0410x over previous
#include <cuda_runtime.h>
#include <math.h>

#define BB 2
#define HH 8
#define NN 512
#define DD 64
#define TT 512      // DFT input (nonzero) length
#define MM 512      // DFT output frequencies kept
#define CC 2048     // GEMM columns: 2 tensors * 16 bh * 64 j

#define X_ELEMS   (BB*NN*512)   // 524288
#define W_ELEMS   (512*512)     // 262144
#define OUT_F2    (BB*HH*NN*DD) // 524288 complex outputs

__device__ __forceinline__ int iclamp(int i, int n) { return i < n ? (i < 0 ? 0 : i) : n - 1; }

// ---------------- scratch ----------------
__device__ float g_kraw[BB*NN*512];
__device__ float g_v   [BB*NN*512];
__device__ float g_part[128];
__device__ float g_Ac[256*TT];        // cos rows m=0..255
__device__ float g_As[256*TT];        // -sin rows m=0..255
__device__ float g_inb[TT*CC];
__device__ float g_re [MM*CC];
__device__ float g_im [MM*CC];

// ---------------- K1: merged projections k = x@Wk, v = x@Wv ----------------
__global__ void k_proj(const float* __restrict__ X,
                       const float* __restrict__ Wkm,
                       const float* __restrict__ Wvm) {
    const int tidx = threadIdx.x;          // 256 threads
    const int tx = tidx & 15, ty = tidx >> 4;
    const int n0 = blockIdx.x * 64;
    const int m0 = blockIdx.y * 64;

    __shared__ float sA [16][65];
    __shared__ float sBk[16][64];
    __shared__ float sBv[16][64];
    __shared__ float sred[256];
    float ack[4][4] = {};
    float acv[4][4] = {};

    for (int k0 = 0; k0 < 512; k0 += 16) {
        int ak = tidx & 15, am = tidx >> 4;
#pragma unroll
        for (int i = 0; i < 4; i++)
            sA[ak][am + i*16] = X[iclamp((m0 + am + i*16)*512 + k0 + ak, X_ELEMS)];
        int bn = tidx & 63, bk = tidx >> 6;
#pragma unroll
        for (int i = 0; i < 4; i++) {
            int widx = iclamp((k0 + bk + i*4)*512 + n0 + bn, W_ELEMS);
            sBk[bk + i*4][bn] = Wkm[widx];
            sBv[bk + i*4][bn] = Wvm[widx];
        }
        __syncthreads();
#pragma unroll
        for (int kk = 0; kk < 16; kk++) {
            float a4[4], bk4[4], bv4[4];
#pragma unroll
            for (int r = 0; r < 4; r++) a4[r] = sA[kk][ty + 16*r];
#pragma unroll
            for (int c = 0; c < 4; c++) { bk4[c] = sBk[kk][tx + 16*c]; bv4[c] = sBv[kk][tx + 16*c]; }
#pragma unroll
            for (int r = 0; r < 4; r++)
#pragma unroll
                for (int c = 0; c < 4; c++) {
                    ack[r][c] += a4[r] * bk4[c];
                    acv[r][c] += a4[r] * bv4[c];
                }
        }
        __syncthreads();
    }

    float nsum = 0.f;
#pragma unroll
    for (int r = 0; r < 4; r++)
#pragma unroll
        for (int c = 0; c < 4; c++) {
            int o = (m0 + ty + 16*r)*512 + n0 + tx + 16*c;
            g_kraw[o] = ack[r][c];
            g_v[o]    = acv[r][c];
            nsum += ack[r][c] * ack[r][c];
        }
    sred[tidx] = nsum; __syncthreads();
    for (int o = 128; o > 0; o >>= 1) {
        if (tidx < o) sred[tidx] += sred[tidx + o];
        __syncthreads();
    }
    if (tidx == 0) g_part[blockIdx.y*8 + blockIdx.x] = sred[0];
}

// ---------------- K3: rnorm + elu + per-head sums + pack B + build DFT table ----------
__global__ void k_prep() {
    int bt = blockIdx.x;           // b*512 + t
    int b  = bt >> 9;
    int t  = bt & 511;
    int tid = threadIdx.x;         // 0..511 = h*64 + j

    __shared__ float rs[128];
    __shared__ float sh_rn;
    if (tid < 128) rs[tid] = g_part[tid];
    __syncthreads();
    if (tid == 0) {
        float s = 0.f;
#pragma unroll 8
        for (int i = 0; i < 128; i++) s += rs[i];
        sh_rn = 1.0f / sqrtf(s);
    }
    if (bt < 256) {
        int k = (bt * tid) & 1023;
        float sn, cn;
        sincospif((float)k * (1.0f / 512.0f), &sn, &cn);
        g_Ac[bt*TT + tid] = cn;
        g_As[bt*TT + tid] = -sn;
    }
    __syncthreads();
    float rn = sh_rn;

    float kv = g_kraw[bt*512 + tid] * rn;
    float ke = kv > 0.f ? kv : expm1f(kv);

    float s = ke;
#pragma unroll
    for (int o = 16; o > 0; o >>= 1) s += __shfl_down_sync(0xffffffffu, s, o);
    __shared__ float wsum[16];
    __shared__ float hsum[8];
    int warp = tid >> 5;
    if ((tid & 31) == 0) wsum[warp] = s;
    __syncthreads();
    if (tid < 8) hsum[tid] = wsum[2*tid] + wsum[2*tid + 1];
    __syncthreads();

    int h = tid >> 6;
    float u = hsum[h] * g_v[bt*512 + tid];
    g_inb[t*CC + b*512 + tid]        = u;    // numerator tensor
    g_inb[t*CC + 1024 + b*512 + tid] = ke;   // denominator tensor
}

// ---------------- K4: octo-row DFT GEMM via mod-8 t-class split ----------------
// Base rows m in 0..64 -> rows m, 128-m, 128+m, 256-m, 256+m, 384-m, 384+m, 512-m.
// C_p = sum_{t=p mod 8} b cos(theta_m), S_p = sum b sin(theta_m) (g_As stores -sin).
__global__ void k_dft() {
    const int tidx = threadIdx.x;          // 256 threads
    const int tx = tidx & 15;              // 16 col groups of 4
    const int ty = tidx >> 4;              // 16 rows, 1 per thread
    const int n0 = blockIdx.x * 64;        // col base
    const int m0 = blockIdx.y * 16;        // row base: 0,16,32,48,64

    __shared__ float sAc[16][17];          // cos  [t][row]
    __shared__ float sAn[16][17];          // -sin [t][row]
    __shared__ float sB [16][64];

    float C [8][4] = {};
    float Nn[8][4] = {};                   // -sin sums; S_p = -Nn_p

    for (int k0 = 0; k0 < 512; k0 += 16) {
        {
            int t = tidx & 15, row = tidx >> 4;
            int idx = (m0 + row)*TT + k0 + t;
            sAc[t][row] = g_Ac[idx];
            sAn[t][row] = g_As[idx];
        }
        {
            int c = tidx & 63, tb = tidx >> 6;
#pragma unroll
            for (int i = 0; i < 4; i++)
                sB[tb + i*4][c] = g_inb[(k0 + tb + i*4)*CC + n0 + c];
        }
        __syncthreads();
#pragma unroll
        for (int kk = 0; kk < 16; kk++) {      // t class p = kk & 7 (k0 % 8 == 0)
            const int p = kk & 7;
            float c = sAc[kk][ty];
            float s = sAn[kk][ty];
            float4 b4 = *(const float4*)&sB[kk][tx*4];
            C [p][0] += c*b4.x; C [p][1] += c*b4.y; C [p][2] += c*b4.z; C [p][3] += c*b4.w;
            Nn[p][0] += s*b4.x; Nn[p][1] += s*b4.y; Nn[p][2] += s*b4.z; Nn[p][3] += s*b4.w;
        }
        __syncthreads();
    }

    const int mp = m0 + ty;                    // base row (useful: 0..64)
    const float R = 0.70710678118654752f;
#pragma unroll
    for (int cc = 0; cc < 4; cc++) {
        int col = n0 + tx*4 + cc;
        float C0=C[0][cc],C1=C[1][cc],C2=C[2][cc],C3=C[3][cc];
        float C4=C[4][cc],C5=C[5][cc],C6=C[6][cc],C7=C[7][cc];
        float S0=-Nn[0][cc],S1=-Nn[1][cc],S2=-Nn[2][cc],S3=-Nn[3][cc];
        float S4=-Nn[4][cc],S5=-Nn[5][cc],S6=-Nn[6][cc],S7=-Nn[7][cc];
        float T0c=C0+C4,T1c=C1+C5,T2c=C2+C6,T3c=C3+C7;
        float T0s=S0+S4,T1s=S1+S5,T2s=S2+S6,T3s=S3+S7;
        float U0c=C0-C4,U1c=C1-C5,U2c=C2-C6,U3c=C3-C7;
        float U0s=S0-S4,U1s=S1-S5,U2s=S2-S6,U3s=S3-S7;

        if (mp <= 64) {                                   // row m
            int o = mp*CC + col;
            g_re[o] = T0c+T1c+T2c+T3c;
            g_im[o] = -(T0s+T1s+T2s+T3s);
        }
        if (mp >= 1 && mp <= 64) {                        // row 512-m
            int o = (512-mp)*CC + col;
            g_re[o] = T0c-T1c+T2c-T3c;
            g_im[o] = T0s-T1s+T2s-T3s;
        }
        if (mp <= 63) {                                   // row 256-m
            int o = (256-mp)*CC + col;
            g_re[o] = (T0c-T2c) + (T1s-T3s);
            g_im[o] = (T0s-T2s) - (T1c-T3c);
        }
        if (mp >= 1 && mp <= 64) {                        // row 256+m
            int o = (256+mp)*CC + col;
            g_re[o] = (T0c-T2c) - (T1s-T3s);
            g_im[o] = -((T0s-T2s) + (T1c-T3c));
        }
        if (mp <= 63) {                                   // row 128-m
            int o = (128-mp)*CC + col;
            g_re[o] = U0c + U2s + R*((U1c+U1s) + (U3s-U3c));
            g_im[o] = -(-U0s + U2c + R*((U1c-U1s) + (U3c+U3s)));
        }
        if (mp >= 1 && mp <= 64) {                        // row 128+m (FIXED: U3c-U3s)
            int o = (128+mp)*CC + col;
            g_re[o] = U0c - U2s + R*((U1c-U1s) - (U3c+U3s));
            g_im[o] = -(U0s + U2c + R*((U1c+U1s) + (U3c-U3s)));
        }
        if (mp <= 63) {                                   // row 384-m
            int o = (384-mp)*CC + col;
            g_re[o] = U0c - U2s + R*((U1s-U1c) + (U3c+U3s));
            g_im[o] = -(-U0s - U2c + R*((U1c+U1s) + (U3c-U3s)));
        }
        if (mp >= 1 && mp <= 63) {                        // row 384+m
            int o = (384+mp)*CC + col;
            g_re[o] = U0c + U2s - R*(U1c+U1s) + R*(U3c-U3s);
            g_im[o] = -(U0s - U2c + R*((U1c-U1s) + (U3c+U3s)));
        }
    }
}

// ---------------- K5: (b,h) 2x8 DFT mix + complex division ----------------
__global__ void k_mix(float* __restrict__ out, int cap_floats, int mode) {
    int m = blockIdx.x;      // 0..511
    int j = threadIdx.x;     // 0..63

    float pur[16], pui[16], pkr[16], pki[16];
#pragma unroll
    for (int bh = 0; bh < 16; bh++) {
        int cu = m*CC + bh*64 + j;
        pur[bh] = g_re[cu];        pui[bh] = g_im[cu];
        pkr[bh] = g_re[cu + 1024]; pki[bh] = g_im[cu + 1024];
    }

    const float R2 = 0.70710678118654752f;
    const float w8r[8] = {1.f,  R2, 0.f, -R2, -1.f, -R2, 0.f,  R2};
    const float w8i[8] = {0.f, -R2, -1.f, -R2, 0.f,  R2, 1.f,  R2};

#pragma unroll
    for (int h0 = 0; h0 < 8; h0++) {
        float eur=0,eui=0,our_=0,oui=0, ekr=0,eki=0,okr=0,oki=0;
#pragma unroll
        for (int hp = 0; hp < 8; hp++) {
            int kq = (h0 * hp) & 7;
            float wr = w8r[kq], wi = w8i[kq];
            eur  += wr*pur[hp]   - wi*pui[hp];
            eui  += wr*pui[hp]   + wi*pur[hp];
            our_ += wr*pur[8+hp] - wi*pui[8+hp];
            oui  += wr*pui[8+hp] + wi*pur[8+hp];
            ekr  += wr*pkr[hp]   - wi*pki[hp];
            eki  += wr*pki[hp]   + wi*pkr[hp];
            okr  += wr*pkr[8+hp] - wi*pki[8+hp];
            oki  += wr*pki[8+hp] + wi*pkr[8+hp];
        }
#pragma unroll
        for (int b0 = 0; b0 < 2; b0++) {
            float sg = b0 ? -1.f : 1.f;
            float nr = eur + sg*our_, ni = eui + sg*oui;
            float dr = ekr + sg*okr,  di = eki + sg*oki;
            float inv = 1.0f / (dr*dr + di*di);
            float orr = (nr*dr + ni*di) * inv;
            float oii = (ni*dr - nr*di) * inv;
            int idx = (((b0*8 + h0)*512 + m)*64) + j;
            if (mode) {
                int f = 2*idx;
                if (f + 1 < cap_floats) { out[f] = orr; out[f+1] = oii; }
            } else {
                if (idx < cap_floats) out[idx] = orr;
            }
        }
    }
}

// ---------------- launch ----------------
extern "C" void kernel_launch(void* const* d_in, const int* in_sizes, int n_in,
                              void* d_out, int out_size) {
    const float* x = nullptr;
    const float* Ws[3] = {nullptr, nullptr, nullptr};

    int xi = -1; long long xmax = -1;
    for (int i = 0; i < n_in; i++)
        if ((long long)in_sizes[i] > xmax) { xmax = in_sizes[i]; xi = i; }
    if (xi >= 0) x = (const float*)d_in[xi];

    int wcount = 0;
    for (int i = 0; i < n_in && wcount < 3; i++) {
        if (i == xi) continue;
        int same = 0;
        for (int k2 = 0; k2 < n_in; k2++)
            if (k2 != xi && in_sizes[k2] == in_sizes[i]) same++;
        if (same == 3) Ws[wcount++] = (const float*)d_in[i];
    }
    if ((!Ws[0] || !Ws[1] || !Ws[2]) && n_in >= 4) {
        x = (const float*)d_in[0];
        Ws[0] = (const float*)d_in[1];
        Ws[1] = (const float*)d_in[2];
        Ws[2] = (const float*)d_in[3];
    }
    const float* Wk = Ws[1];
    const float* Wv = Ws[2];
    if (!x || !Wk || !Wv || !d_out || out_size <= 0) return;

    int mode, cap_floats;
    if (out_size >= 2*OUT_F2) { mode = 1; cap_floats = 2*OUT_F2; }
    else                      { mode = 0; cap_floats = out_size < OUT_F2 ? out_size : OUT_F2; }

    k_proj<<<dim3(8, 16), 256>>>(x, Wk, Wv);
    k_prep<<<1024, 512>>>();
    k_dft<<<dim3(32, 5), 256>>>();
    k_mix<<<512, 64>>>((float*)d_out, cap_floats, mode);
}

// round 10
// speedup vs baseline: 2.5470x; 1.0617x over previous
#include <cuda_runtime.h>
#include <math.h>

#define BB 2
#define HH 8
#define NN 512
#define DD 64
#define TT 512      // DFT input (nonzero) length
#define MM 512      // DFT output frequencies kept
#define CC 2048     // GEMM columns: 2 tensors * 16 bh * 64 j

#define X_ELEMS   (BB*NN*512)   // 524288
#define W_ELEMS   (512*512)     // 262144
#define OUT_F2    (BB*HH*NN*DD) // 524288 complex outputs

__device__ __forceinline__ int iclamp(int i, int n) { return i < n ? (i < 0 ? 0 : i) : n - 1; }

// ---------------- scratch ----------------
__device__ float g_kraw[BB*NN*512];
__device__ float g_v   [BB*NN*512];
__device__ float g_part[128];
__device__ float g_Ac[256*TT];        // cos rows m=0..255
__device__ float g_As[256*TT];        // -sin rows m=0..255
__device__ float g_inb[TT*CC];
__device__ float g_re [MM*CC];
__device__ float g_im [MM*CC];

// ---------------- K1: merged projections k = x@Wk, v = x@Wv ----------------
__global__ void k_proj(const float* __restrict__ X,
                       const float* __restrict__ Wkm,
                       const float* __restrict__ Wvm) {
    const int tidx = threadIdx.x;          // 256 threads
    const int tx = tidx & 15, ty = tidx >> 4;
    const int n0 = blockIdx.x * 64;
    const int m0 = blockIdx.y * 64;

    __shared__ float sA [16][65];
    __shared__ float sBk[16][64];
    __shared__ float sBv[16][64];
    __shared__ float sred[256];
    float ack[4][4] = {};
    float acv[4][4] = {};

    for (int k0 = 0; k0 < 512; k0 += 16) {
        int ak = tidx & 15, am = tidx >> 4;
#pragma unroll
        for (int i = 0; i < 4; i++)
            sA[ak][am + i*16] = X[iclamp((m0 + am + i*16)*512 + k0 + ak, X_ELEMS)];
        int bn = tidx & 63, bk = tidx >> 6;
#pragma unroll
        for (int i = 0; i < 4; i++) {
            int widx = iclamp((k0 + bk + i*4)*512 + n0 + bn, W_ELEMS);
            sBk[bk + i*4][bn] = Wkm[widx];
            sBv[bk + i*4][bn] = Wvm[widx];
        }
        __syncthreads();
#pragma unroll
        for (int kk = 0; kk < 16; kk++) {
            float a4[4], bk4[4], bv4[4];
#pragma unroll
            for (int r = 0; r < 4; r++) a4[r] = sA[kk][ty + 16*r];
#pragma unroll
            for (int c = 0; c < 4; c++) { bk4[c] = sBk[kk][tx + 16*c]; bv4[c] = sBv[kk][tx + 16*c]; }
#pragma unroll
            for (int r = 0; r < 4; r++)
#pragma unroll
                for (int c = 0; c < 4; c++) {
                    ack[r][c] += a4[r] * bk4[c];
                    acv[r][c] += a4[r] * bv4[c];
                }
        }
        __syncthreads();
    }

    float nsum = 0.f;
#pragma unroll
    for (int r = 0; r < 4; r++)
#pragma unroll
        for (int c = 0; c < 4; c++) {
            int o = (m0 + ty + 16*r)*512 + n0 + tx + 16*c;
            g_kraw[o] = ack[r][c];
            g_v[o]    = acv[r][c];
            nsum += ack[r][c] * ack[r][c];
        }
    sred[tidx] = nsum; __syncthreads();
    for (int o = 128; o > 0; o >>= 1) {
        if (tidx < o) sred[tidx] += sred[tidx + o];
        __syncthreads();
    }
    if (tidx == 0) g_part[blockIdx.y*8 + blockIdx.x] = sred[0];
}

// ---------------- K3: rnorm + elu + per-head sums + pack B + build DFT table ----------
__global__ void k_prep() {
    int bt = blockIdx.x;           // b*512 + t
    int b  = bt >> 9;
    int t  = bt & 511;
    int tid = threadIdx.x;         // 0..511 = h*64 + j

    __shared__ float rs[128];
    __shared__ float sh_rn;
    if (tid < 128) rs[tid] = g_part[tid];
    // build DFT matrix row m=bt (blocks 0..255); independent of rnorm
    if (bt < 256) {
        int k = (bt * tid) & 1023;
        float sn, cn;
        sincospif((float)k * (1.0f / 512.0f), &sn, &cn);
        g_Ac[bt*TT + tid] = cn;
        g_As[bt*TT + tid] = -sn;
    }
    __syncthreads();
    if (tid < 64) rs[tid] += rs[tid + 64];
    __syncthreads();
    if (tid < 32) {
        float v = rs[tid] + rs[tid + 32];
#pragma unroll
        for (int o = 16; o > 0; o >>= 1) v += __shfl_down_sync(0xffffffffu, v, o);
        if (tid == 0) sh_rn = rsqrtf(v);
    }
    __syncthreads();
    float rn = sh_rn;

    float kv = g_kraw[bt*512 + tid] * rn;
    float ke = kv > 0.f ? kv : expm1f(kv);

    float s = ke;
#pragma unroll
    for (int o = 16; o > 0; o >>= 1) s += __shfl_down_sync(0xffffffffu, s, o);
    __shared__ float wsum[16];
    __shared__ float hsum[8];
    int warp = tid >> 5;
    if ((tid & 31) == 0) wsum[warp] = s;
    __syncthreads();
    if (tid < 8) hsum[tid] = wsum[2*tid] + wsum[2*tid + 1];
    __syncthreads();

    int h = tid >> 6;
    float u = hsum[h] * g_v[bt*512 + tid];
    g_inb[t*CC + b*512 + tid]        = u;    // numerator tensor
    g_inb[t*CC + 1024 + b*512 + tid] = ke;   // denominator tensor
}

// ---------------- K4: octo-row DFT GEMM, single wave (base rows 1..64) ----------------
// grid (32, 4) = 128 blocks. Base rows m = 16*by + ty + 1 -> rows m, 128+-m, 256+-m,
// 384+-m, 512-m. Rows {0,128,256,384} come from mod-8 class sums P_p (warp 0 of y==0
// blocks accumulates them; theta multiples of pi/4 -> pure +-/R combos).
__global__ void k_dft() {
    const int tidx = threadIdx.x;          // 256 threads
    const int tx = tidx & 15;              // 16 col groups of 4
    const int ty = tidx >> 4;              // 16 rows
    const int n0 = blockIdx.x * 64;        // col base
    const int m0 = blockIdx.y * 16 + 1;    // row base: 1,17,33,49

    __shared__ float sAc[16][17];
    __shared__ float sAn[16][17];
    __shared__ float sB [16][64];

    float C [8][4] = {};
    float Nn[8][4] = {};                   // -sin sums; S_p = -Nn_p
    float P [8][4] = {};                   // class sums (warp 0 of y==0 blocks only)
    const bool doP = (blockIdx.y == 0) && (ty < 2);   // warp-uniform

    for (int k0 = 0; k0 < 512; k0 += 16) {
        {
            int t = tidx & 15, row = tidx >> 4;
            int idx = (m0 + row)*TT + k0 + t;
            sAc[t][row] = g_Ac[idx];
            sAn[t][row] = g_As[idx];
        }
        {
            int c = tidx & 63, tb = tidx >> 6;
#pragma unroll
            for (int i = 0; i < 4; i++)
                sB[tb + i*4][c] = g_inb[(k0 + tb + i*4)*CC + n0 + c];
        }
        __syncthreads();
#pragma unroll
        for (int kk = 0; kk < 16; kk++) {      // t class p = kk & 7
            const int p = kk & 7;
            float c = sAc[kk][ty];
            float s = sAn[kk][ty];
            float4 b4 = *(const float4*)&sB[kk][tx*4];
            C [p][0] += c*b4.x; C [p][1] += c*b4.y; C [p][2] += c*b4.z; C [p][3] += c*b4.w;
            Nn[p][0] += s*b4.x; Nn[p][1] += s*b4.y; Nn[p][2] += s*b4.z; Nn[p][3] += s*b4.w;
            if (doP) {
                P[p][0] += b4.x; P[p][1] += b4.y; P[p][2] += b4.z; P[p][3] += b4.w;
            }
        }
        __syncthreads();
    }

    const int mp = m0 + ty;                    // base row: 1..64
    const float R = 0.70710678118654752f;
#pragma unroll
    for (int cc = 0; cc < 4; cc++) {
        int col = n0 + tx*4 + cc;
        float C0=C[0][cc],C1=C[1][cc],C2=C[2][cc],C3=C[3][cc];
        float C4=C[4][cc],C5=C[5][cc],C6=C[6][cc],C7=C[7][cc];
        float S0=-Nn[0][cc],S1=-Nn[1][cc],S2=-Nn[2][cc],S3=-Nn[3][cc];
        float S4=-Nn[4][cc],S5=-Nn[5][cc],S6=-Nn[6][cc],S7=-Nn[7][cc];
        float T0c=C0+C4,T1c=C1+C5,T2c=C2+C6,T3c=C3+C7;
        float T0s=S0+S4,T1s=S1+S5,T2s=S2+S6,T3s=S3+S7;
        float U0c=C0-C4,U1c=C1-C5,U2c=C2-C6,U3c=C3-C7;
        float U0s=S0-S4,U1s=S1-S5,U2s=S2-S6,U3s=S3-S7;

        {                                                 // row m (1..64)
            int o = mp*CC + col;
            g_re[o] = T0c+T1c+T2c+T3c;
            g_im[o] = -(T0s+T1s+T2s+T3s);
        }
        {                                                 // row 512-m (448..511)
            int o = (512-mp)*CC + col;
            g_re[o] = T0c-T1c+T2c-T3c;
            g_im[o] = T0s-T1s+T2s-T3s;
        }
        if (mp <= 63) {                                   // row 256-m (193..255)
            int o = (256-mp)*CC + col;
            g_re[o] = (T0c-T2c) + (T1s-T3s);
            g_im[o] = (T0s-T2s) - (T1c-T3c);
        }
        {                                                 // row 256+m (257..320)
            int o = (256+mp)*CC + col;
            g_re[o] = (T0c-T2c) - (T1s-T3s);
            g_im[o] = -((T0s-T2s) + (T1c-T3c));
        }
        if (mp <= 63) {                                   // row 128-m (65..127)
            int o = (128-mp)*CC + col;
            g_re[o] = U0c + U2s + R*((U1c+U1s) + (U3s-U3c));
            g_im[o] = -(-U0s + U2c + R*((U1c-U1s) + (U3c+U3s)));
        }
        {                                                 // row 128+m (129..192)
            int o = (128+mp)*CC + col;
            g_re[o] = U0c - U2s + R*((U1c-U1s) - (U3c+U3s));
            g_im[o] = -(U0s + U2c + R*((U1c+U1s) + (U3c-U3s)));
        }
        if (mp <= 63) {                                   // row 384-m (321..383)
            int o = (384-mp)*CC + col;
            g_re[o] = U0c - U2s + R*((U1s-U1c) + (U3c+U3s));
            g_im[o] = -(-U0s - U2c + R*((U1c+U1s) + (U3c-U3s)));
        }
        if (mp <= 63) {                                   // row 384+m (385..447)
            int o = (384+mp)*CC + col;
            g_re[o] = U0c + U2s - R*(U1c+U1s) + R*(U3c-U3s);
            g_im[o] = -(U0s - U2c + R*((U1c-U1s) + (U3c+U3s)));
        }

        if (blockIdx.y == 0 && ty == 0) {                 // rows 0,128,256,384
            float P0=P[0][cc],P1=P[1][cc],P2=P[2][cc],P3=P[3][cc];
            float P4=P[4][cc],P5=P[5][cc],P6=P[6][cc],P7=P[7][cc];
            float A  = P0 - P4;
            float Bq = P1 - P3 - P5 + P7;
            float Cq = P2 - P6;
            float Dq = P1 + P3 - P5 - P7;
            g_re[col]          = P0+P1+P2+P3+P4+P5+P6+P7;
            g_im[col]          = 0.f;
            g_re[128*CC + col] = A + R*Bq;
            g_im[128*CC + col] = -(Cq + R*Dq);
            g_re[256*CC + col] = P0 - P2 + P4 - P6;
            g_im[256*CC + col] = -(P1 - P3 + P5 - P7);
            g_re[384*CC + col] = A - R*Bq;
            g_im[384*CC + col] = -(-Cq + R*Dq);
        }
    }
}

// ---------------- K5: (b,h) 2x8 DFT mix + complex division ----------------
__global__ void k_mix(float* __restrict__ out, int cap_floats, int mode) {
    int m = blockIdx.x;      // 0..511
    int j = threadIdx.x;     // 0..63

    float pur[16], pui[16], pkr[16], pki[16];
#pragma unroll
    for (int bh = 0; bh < 16; bh++) {
        int cu = m*CC + bh*64 + j;
        pur[bh] = g_re[cu];        pui[bh] = g_im[cu];
        pkr[bh] = g_re[cu + 1024]; pki[bh] = g_im[cu + 1024];
    }

    const float R2 = 0.70710678118654752f;
    const float w8r[8] = {1.f,  R2, 0.f, -R2, -1.f, -R2, 0.f,  R2};
    const float w8i[8] = {0.f, -R2, -1.f, -R2, 0.f,  R2, 1.f,  R2};

#pragma unroll
    for (int h0 = 0; h0 < 8; h0++) {
        float eur=0,eui=0,our_=0,oui=0, ekr=0,eki=0,okr=0,oki=0;
#pragma unroll
        for (int hp = 0; hp < 8; hp++) {
            int kq = (h0 * hp) & 7;
            float wr = w8r[kq], wi = w8i[kq];
            eur  += wr*pur[hp]   - wi*pui[hp];
            eui  += wr*pui[hp]   + wi*pur[hp];
            our_ += wr*pur[8+hp] - wi*pui[8+hp];
            oui  += wr*pui[8+hp] + wi*pur[8+hp];
            ekr  += wr*pkr[hp]   - wi*pki[hp];
            eki  += wr*pki[hp]   + wi*pkr[hp];
            okr  += wr*pkr[8+hp] - wi*pki[8+hp];
            oki  += wr*pki[8+hp] + wi*pkr[8+hp];
        }
#pragma unroll
        for (int b0 = 0; b0 < 2; b0++) {
            float sg = b0 ? -1.f : 1.f;
            float nr = eur + sg*our_, ni = eui + sg*oui;
            float dr = ekr + sg*okr,  di = eki + sg*oki;
            float inv = 1.0f / (dr*dr + di*di);
            float orr = (nr*dr + ni*di) * inv;
            float oii = (ni*dr - nr*di) * inv;
            int idx = (((b0*8 + h0)*512 + m)*64) + j;
            if (mode) {
                int f = 2*idx;
                if (f + 1 < cap_floats) { out[f] = orr; out[f+1] = oii; }
            } else {
                if (idx < cap_floats) out[idx] = orr;
            }
        }
    }
}

// ---------------- launch ----------------
extern "C" void kernel_launch(void* const* d_in, const int* in_sizes, int n_in,
                              void* d_out, int out_size) {
    const float* x = nullptr;
    const float* Ws[3] = {nullptr, nullptr, nullptr};

    int xi = -1; long long xmax = -1;
    for (int i = 0; i < n_in; i++)
        if ((long long)in_sizes[i] > xmax) { xmax = in_sizes[i]; xi = i; }
    if (xi >= 0) x = (const float*)d_in[xi];

    int wcount = 0;
    for (int i = 0; i < n_in && wcount < 3; i++) {
        if (i == xi) continue;
        int same = 0;
        for (int k2 = 0; k2 < n_in; k2++)
            if (k2 != xi && in_sizes[k2] == in_sizes[i]) same++;
        if (same == 3) Ws[wcount++] = (const float*)d_in[i];
    }
    if ((!Ws[0] || !Ws[1] || !Ws[2]) && n_in >= 4) {
        x = (const float*)d_in[0];
        Ws[0] = (const float*)d_in[1];
        Ws[1] = (const float*)d_in[2];
        Ws[2] = (const float*)d_in[3];
    }
    const float* Wk = Ws[1];
    const float* Wv = Ws[2];
    if (!x || !Wk || !Wv || !d_out || out_size <= 0) return;

    int mode, cap_floats;
    if (out_size >= 2*OUT_F2) { mode = 1; cap_floats = 2*OUT_F2; }
    else                      { mode = 0; cap_floats = out_size < OUT_F2 ? out_size : OUT_F2; }

    k_proj<<<dim3(8, 16), 256>>>(x, Wk, Wv);
    k_prep<<<1024, 512>>>();
    k_dft<<<dim3(32, 4), 256>>>();
    k_mix<<<512, 64>>>((float*)d_out, cap_floats, mode);
}

// round 12
// speedup vs baseline: 3.6472x; 1.4319x over previous
#include <cuda_runtime.h>
#include <cuda_bf16.h>
#include <math.h>
#include <stdint.h>

#define BB 2
#define HH 8
#define NN 512
#define TT 512
#define MM 512
#define CC 2048

#define X_ELEMS   (BB*NN*512)
#define OUT_F2    (BB*HH*NN*64)

// ---------------- scratch ----------------
__device__ float g_kraw[BB*NN*512];
__device__ float g_v   [BB*NN*512];
__device__ float g_part[128];
__device__ float g_Ac[256*TT];
__device__ float g_As[256*TT];
__device__ float g_inb[TT*CC];
__device__ float g_re [MM*CC];
__device__ float g_im [MM*CC];

__device__ __forceinline__ uint32_t pack_bf2(__nv_bfloat16 a, __nv_bfloat16 b) {
    __nv_bfloat162 t(a, b);
    return *reinterpret_cast<uint32_t*>(&t);
}
__device__ __forceinline__ void split4(float4 v, uint2& hi, uint2& lo) {
    __nv_bfloat16 h0 = __float2bfloat16(v.x), h1 = __float2bfloat16(v.y);
    __nv_bfloat16 h2 = __float2bfloat16(v.z), h3 = __float2bfloat16(v.w);
    __nv_bfloat16 l0 = __float2bfloat16(v.x - __bfloat162float(h0));
    __nv_bfloat16 l1 = __float2bfloat16(v.y - __bfloat162float(h1));
    __nv_bfloat16 l2 = __float2bfloat16(v.z - __bfloat162float(h2));
    __nv_bfloat16 l3 = __float2bfloat16(v.w - __bfloat162float(h3));
    hi.x = pack_bf2(h0, h1); hi.y = pack_bf2(h2, h3);
    lo.x = pack_bf2(l0, l1); lo.y = pack_bf2(l2, l3);
}
__device__ __forceinline__ void split1(float v, uint16_t& hi, uint16_t& lo) {
    __nv_bfloat16 h = __float2bfloat16(v);
    __nv_bfloat16 l = __float2bfloat16(v - __bfloat162float(h));
    hi = *reinterpret_cast<uint16_t*>(&h);
    lo = *reinterpret_cast<uint16_t*>(&l);
}
__device__ __forceinline__ void mma_bf16(float d[4], const uint32_t a[4], const uint32_t b[2]) {
    asm volatile(
        "mma.sync.aligned.m16n8k16.row.col.f32.bf16.bf16.f32 "
        "{%0,%1,%2,%3}, {%4,%5,%6,%7}, {%8,%9}, {%0,%1,%2,%3};"
        : "+f"(d[0]), "+f"(d[1]), "+f"(d[2]), "+f"(d[3])
        : "r"(a[0]), "r"(a[1]), "r"(a[2]), "r"(a[3]), "r"(b[0]), "r"(b[1]));
}

// ---------------- K1: projections via mma.sync bf16x3 ----------------
// grid (16, 8): bn 0..7 -> Wk cols bn*64; bn 8..15 -> Wv cols (bn-8)*64. bm -> rows bm*128.
// Block tile 128m x 64n, K=512 in 32 chunks of 16. 8 warps = 4m x 2n, warp tile 32x32.
#define ASTRIDE 48   // bytes per 16-k bf16 row (32B data + 16B pad) -> conflict-free frags
__global__ void k_proj_mma(const float* __restrict__ X,
                           const float* __restrict__ Wkm,
                           const float* __restrict__ Wvm) {
    __shared__ __align__(16) char sAh[128*ASTRIDE];
    __shared__ __align__(16) char sAl[128*ASTRIDE];
    __shared__ __align__(16) char sBh[64*ASTRIDE];
    __shared__ __align__(16) char sBl[64*ASTRIDE];
    __shared__ float sred[8];

    const int tid = threadIdx.x, wid = tid >> 5, lid = tid & 31;
    const int bn = blockIdx.x, bm = blockIdx.y;
    const int m0 = bm * 128;
    const bool isK = (bn < 8);
    const float* Wm = isK ? Wkm : Wvm;
    const int n0 = (bn & 7) * 64;

    const int g  = lid >> 2;         // 0..7
    const int tg = lid & 3;          // 0..3
    const int wm = (wid & 3) * 32;   // warp m offset
    const int wn = (wid >> 2) * 32;  // warp n offset

    float d[2][4][4] = {};           // [mt][nt][reg]

    for (int c = 0; c < 32; c++) {
        const int k0 = c * 16;
        // ---- X tile: 128 rows x 16 k (fp32 -> bf16 hi/lo) ----
#pragma unroll
        for (int it = 0; it < 2; it++) {
            int i = tid + it * 256;            // 0..511
            int r = i >> 2, kq = i & 3;
            float4 xv = *(const float4*)(X + (m0 + r) * 512 + k0 + kq * 4);
            uint2 hi, lo; split4(xv, hi, lo);
            *(uint2*)(sAh + r * ASTRIDE + kq * 8) = hi;
            *(uint2*)(sAl + r * ASTRIDE + kq * 8) = lo;
        }
        // ---- W tile: 16 k x 64 n -> sB[n][k] (transpose + split) ----
        {
            int n = tid & 63, kq = tid >> 6;   // kq 0..3
#pragma unroll
            for (int j = 0; j < 4; j++) {
                int kk = kq * 4 + j;
                float wv = Wm[(size_t)(k0 + kk) * 512 + n0 + n];
                uint16_t hi, lo; split1(wv, hi, lo);
                *(uint16_t*)(sBh + n * ASTRIDE + kk * 2) = hi;
                *(uint16_t*)(sBl + n * ASTRIDE + kk * 2) = lo;
            }
        }
        __syncthreads();

        // ---- fragment loads ----
        uint32_t ah[2][4], al[2][4], bh[4][2], bl[4][2];
#pragma unroll
        for (int mt = 0; mt < 2; mt++) {
            int r0 = (wm + mt * 16 + g) * ASTRIDE;
            int r1 = (wm + mt * 16 + g + 8) * ASTRIDE;
            ah[mt][0] = *(uint32_t*)(sAh + r0 + tg * 4);
            ah[mt][1] = *(uint32_t*)(sAh + r1 + tg * 4);
            ah[mt][2] = *(uint32_t*)(sAh + r0 + 16 + tg * 4);
            ah[mt][3] = *(uint32_t*)(sAh + r1 + 16 + tg * 4);
            al[mt][0] = *(uint32_t*)(sAl + r0 + tg * 4);
            al[mt][1] = *(uint32_t*)(sAl + r1 + tg * 4);
            al[mt][2] = *(uint32_t*)(sAl + r0 + 16 + tg * 4);
            al[mt][3] = *(uint32_t*)(sAl + r1 + 16 + tg * 4);
        }
#pragma unroll
        for (int nt = 0; nt < 4; nt++) {
            int rn = (wn + nt * 8 + g) * ASTRIDE;
            bh[nt][0] = *(uint32_t*)(sBh + rn + tg * 4);
            bh[nt][1] = *(uint32_t*)(sBh + rn + 16 + tg * 4);
            bl[nt][0] = *(uint32_t*)(sBl + rn + tg * 4);
            bl[nt][1] = *(uint32_t*)(sBl + rn + 16 + tg * 4);
        }
        __syncthreads();

        // ---- 3-term mma ----
#pragma unroll
        for (int mt = 0; mt < 2; mt++)
#pragma unroll
            for (int nt = 0; nt < 4; nt++) {
                mma_bf16(d[mt][nt], ah[mt], bh[nt]);
                mma_bf16(d[mt][nt], ah[mt], bl[nt]);
                mma_bf16(d[mt][nt], al[mt], bh[nt]);
            }
    }

    // ---- epilogue: store D + norm partial ----
    float* outp = isK ? g_kraw : g_v;
    float nsum = 0.f;
#pragma unroll
    for (int mt = 0; mt < 2; mt++)
#pragma unroll
        for (int nt = 0; nt < 4; nt++) {
            int mr = m0 + wm + mt * 16 + g;
            int nc = n0 + wn + nt * 8 + tg * 2;
            *(float2*)(outp + (size_t)mr * 512 + nc)       = make_float2(d[mt][nt][0], d[mt][nt][1]);
            *(float2*)(outp + (size_t)(mr + 8) * 512 + nc) = make_float2(d[mt][nt][2], d[mt][nt][3]);
            nsum += d[mt][nt][0]*d[mt][nt][0] + d[mt][nt][1]*d[mt][nt][1]
                  + d[mt][nt][2]*d[mt][nt][2] + d[mt][nt][3]*d[mt][nt][3];
        }
#pragma unroll
    for (int o = 16; o > 0; o >>= 1) nsum += __shfl_down_sync(0xffffffffu, nsum, o);
    if (lid == 0) sred[wid] = nsum;
    __syncthreads();
    if (tid == 0) {
        float s = 0.f;
#pragma unroll
        for (int w = 0; w < 8; w++) s += sred[w];
        g_part[bm * 16 + bn] = isK ? s : 0.f;
    }
}

// ---------------- K3: rnorm + elu + per-head sums + pack B + build DFT table ----------
__global__ void k_prep() {
    int bt = blockIdx.x;           // b*512 + t
    int b  = bt >> 9;
    int t  = bt & 511;
    int tid = threadIdx.x;         // 0..511 = h*64 + j

    __shared__ float rs[128];
    __shared__ float sh_rn;
    if (tid < 128) rs[tid] = g_part[tid];
    if (bt < 256) {
        int k = (bt * tid) & 1023;
        float sn, cn;
        sincospif((float)k * (1.0f / 512.0f), &sn, &cn);
        g_Ac[bt*TT + tid] = cn;
        g_As[bt*TT + tid] = -sn;
    }
    __syncthreads();
    if (tid < 64) rs[tid] += rs[tid + 64];
    __syncthreads();
    if (tid < 32) {
        float v = rs[tid] + rs[tid + 32];
#pragma unroll
        for (int o = 16; o > 0; o >>= 1) v += __shfl_down_sync(0xffffffffu, v, o);
        if (tid == 0) sh_rn = rsqrtf(v);
    }
    __syncthreads();
    float rn = sh_rn;

    float kv = g_kraw[bt*512 + tid] * rn;
    float ke = kv > 0.f ? kv : expm1f(kv);

    float s = ke;
#pragma unroll
    for (int o = 16; o > 0; o >>= 1) s += __shfl_down_sync(0xffffffffu, s, o);
    __shared__ float wsum[16];
    __shared__ float hsum[8];
    int warp = tid >> 5;
    if ((tid & 31) == 0) wsum[warp] = s;
    __syncthreads();
    if (tid < 8) hsum[tid] = wsum[2*tid] + wsum[2*tid + 1];
    __syncthreads();

    int h = tid >> 6;
    float u = hsum[h] * g_v[bt*512 + tid];
    g_inb[t*CC + b*512 + tid]        = u;
    g_inb[t*CC + 1024 + b*512 + tid] = ke;
}

// ---------------- K4: octo-row DFT GEMM, single wave (base rows 1..64) ----------------
__global__ void k_dft() {
    const int tidx = threadIdx.x;
    const int tx = tidx & 15;
    const int ty = tidx >> 4;
    const int n0 = blockIdx.x * 64;
    const int m0 = blockIdx.y * 16 + 1;

    __shared__ float sAc[16][17];
    __shared__ float sAn[16][17];
    __shared__ float sB [16][64];

    float C [8][4] = {};
    float Nn[8][4] = {};
    float P [8][4] = {};
    const bool doP = (blockIdx.y == 0) && (ty < 2);

    for (int k0 = 0; k0 < 512; k0 += 16) {
        {
            int t = tidx & 15, row = tidx >> 4;
            int idx = (m0 + row)*TT + k0 + t;
            sAc[t][row] = g_Ac[idx];
            sAn[t][row] = g_As[idx];
        }
        {
            int c = tidx & 63, tb = tidx >> 6;
#pragma unroll
            for (int i = 0; i < 4; i++)
                sB[tb + i*4][c] = g_inb[(k0 + tb + i*4)*CC + n0 + c];
        }
        __syncthreads();
#pragma unroll
        for (int kk = 0; kk < 16; kk++) {
            const int p = kk & 7;
            float c = sAc[kk][ty];
            float s = sAn[kk][ty];
            float4 b4 = *(const float4*)&sB[kk][tx*4];
            C [p][0] += c*b4.x; C [p][1] += c*b4.y; C [p][2] += c*b4.z; C [p][3] += c*b4.w;
            Nn[p][0] += s*b4.x; Nn[p][1] += s*b4.y; Nn[p][2] += s*b4.z; Nn[p][3] += s*b4.w;
            if (doP) {
                P[p][0] += b4.x; P[p][1] += b4.y; P[p][2] += b4.z; P[p][3] += b4.w;
            }
        }
        __syncthreads();
    }

    const int mp = m0 + ty;
    const float R = 0.70710678118654752f;
#pragma unroll
    for (int cc = 0; cc < 4; cc++) {
        int col = n0 + tx*4 + cc;
        float C0=C[0][cc],C1=C[1][cc],C2=C[2][cc],C3=C[3][cc];
        float C4=C[4][cc],C5=C[5][cc],C6=C[6][cc],C7=C[7][cc];
        float S0=-Nn[0][cc],S1=-Nn[1][cc],S2=-Nn[2][cc],S3=-Nn[3][cc];
        float S4=-Nn[4][cc],S5=-Nn[5][cc],S6=-Nn[6][cc],S7=-Nn[7][cc];
        float T0c=C0+C4,T1c=C1+C5,T2c=C2+C6,T3c=C3+C7;
        float T0s=S0+S4,T1s=S1+S5,T2s=S2+S6,T3s=S3+S7;
        float U0c=C0-C4,U1c=C1-C5,U2c=C2-C6,U3c=C3-C7;
        float U0s=S0-S4,U1s=S1-S5,U2s=S2-S6,U3s=S3-S7;

        {
            int o = mp*CC + col;
            g_re[o] = T0c+T1c+T2c+T3c;
            g_im[o] = -(T0s+T1s+T2s+T3s);
        }
        {
            int o = (512-mp)*CC + col;
            g_re[o] = T0c-T1c+T2c-T3c;
            g_im[o] = T0s-T1s+T2s-T3s;
        }
        if (mp <= 63) {
            int o = (256-mp)*CC + col;
            g_re[o] = (T0c-T2c) + (T1s-T3s);
            g_im[o] = (T0s-T2s) - (T1c-T3c);
        }
        {
            int o = (256+mp)*CC + col;
            g_re[o] = (T0c-T2c) - (T1s-T3s);
            g_im[o] = -((T0s-T2s) + (T1c-T3c));
        }
        if (mp <= 63) {
            int o = (128-mp)*CC + col;
            g_re[o] = U0c + U2s + R*((U1c+U1s) + (U3s-U3c));
            g_im[o] = -(-U0s + U2c + R*((U1c-U1s) + (U3c+U3s)));
        }
        {
            int o = (128+mp)*CC + col;
            g_re[o] = U0c - U2s + R*((U1c-U1s) - (U3c+U3s));
            g_im[o] = -(U0s + U2c + R*((U1c+U1s) + (U3c-U3s)));
        }
        if (mp <= 63) {
            int o = (384-mp)*CC + col;
            g_re[o] = U0c - U2s + R*((U1s-U1c) + (U3c+U3s));
            g_im[o] = -(-U0s - U2c + R*((U1c+U1s) + (U3c-U3s)));
        }
        if (mp <= 63) {
            int o = (384+mp)*CC + col;
            g_re[o] = U0c + U2s - R*(U1c+U1s) + R*(U3c-U3s);
            g_im[o] = -(U0s - U2c + R*((U1c-U1s) + (U3c+U3s)));
        }

        if (blockIdx.y == 0 && ty == 0) {
            float P0=P[0][cc],P1=P[1][cc],P2=P[2][cc],P3=P[3][cc];
            float P4=P[4][cc],P5=P[5][cc],P6=P[6][cc],P7=P[7][cc];
            float A  = P0 - P4;
            float Bq = P1 - P3 - P5 + P7;
            float Cq = P2 - P6;
            float Dq = P1 + P3 - P5 - P7;
            g_re[col]          = P0+P1+P2+P3+P4+P5+P6+P7;
            g_im[col]          = 0.f;
            g_re[128*CC + col] = A + R*Bq;
            g_im[128*CC + col] = -(Cq + R*Dq);
            g_re[256*CC + col] = P0 - P2 + P4 - P6;
            g_im[256*CC + col] = -(P1 - P3 + P5 - P7);
            g_re[384*CC + col] = A - R*Bq;
            g_im[384*CC + col] = -(-Cq + R*Dq);
        }
    }
}

// ---------------- K5: (b,h) 2x8 DFT mix + complex division ----------------
__global__ void k_mix(float* __restrict__ out, int cap_floats, int mode) {
    int m = blockIdx.x;
    int j = threadIdx.x;

    float pur[16], pui[16], pkr[16], pki[16];
#pragma unroll
    for (int bh = 0; bh < 16; bh++) {
        int cu = m*CC + bh*64 + j;
        pur[bh] = g_re[cu];        pui[bh] = g_im[cu];
        pkr[bh] = g_re[cu + 1024]; pki[bh] = g_im[cu + 1024];
    }

    const float R2 = 0.70710678118654752f;
    const float w8r[8] = {1.f,  R2, 0.f, -R2, -1.f, -R2, 0.f,  R2};
    const float w8i[8] = {0.f, -R2, -1.f, -R2, 0.f,  R2, 1.f,  R2};

#pragma unroll
    for (int h0 = 0; h0 < 8; h0++) {
        float eur=0,eui=0,our_=0,oui=0, ekr=0,eki=0,okr=0,oki=0;
#pragma unroll
        for (int hp = 0; hp < 8; hp++) {
            int kq = (h0 * hp) & 7;
            float wr = w8r[kq], wi = w8i[kq];
            eur  += wr*pur[hp]   - wi*pui[hp];
            eui  += wr*pui[hp]   + wi*pur[hp];
            our_ += wr*pur[8+hp] - wi*pui[8+hp];
            oui  += wr*pui[8+hp] + wi*pur[8+hp];
            ekr  += wr*pkr[hp]   - wi*pki[hp];
            eki  += wr*pki[hp]   + wi*pkr[hp];
            okr  += wr*pkr[8+hp] - wi*pki[8+hp];
            oki  += wr*pki[8+hp] + wi*pkr[8+hp];
        }
#pragma unroll
        for (int b0 = 0; b0 < 2; b0++) {
            float sg = b0 ? -1.f : 1.f;
            float nr = eur + sg*our_, ni = eui + sg*oui;
            float dr = ekr + sg*okr,  di = eki + sg*oki;
            float inv = 1.0f / (dr*dr + di*di);
            float orr = (nr*dr + ni*di) * inv;
            float oii = (ni*dr - nr*di) * inv;
            int idx = (((b0*8 + h0)*512 + m)*64) + j;
            if (mode) {
                int f = 2*idx;
                if (f + 1 < cap_floats) { out[f] = orr; out[f+1] = oii; }
            } else {
                if (idx < cap_floats) out[idx] = orr;
            }
        }
    }
}

// ---------------- launch ----------------
extern "C" void kernel_launch(void* const* d_in, const int* in_sizes, int n_in,
                              void* d_out, int out_size) {
    const float* x = nullptr;
    const float* Ws[3] = {nullptr, nullptr, nullptr};

    int xi = -1; long long xmax = -1;
    for (int i = 0; i < n_in; i++)
        if ((long long)in_sizes[i] > xmax) { xmax = in_sizes[i]; xi = i; }
    if (xi >= 0) x = (const float*)d_in[xi];

    int wcount = 0;
    for (int i = 0; i < n_in && wcount < 3; i++) {
        if (i == xi) continue;
        int same = 0;
        for (int k2 = 0; k2 < n_in; k2++)
            if (k2 != xi && in_sizes[k2] == in_sizes[i]) same++;
        if (same == 3) Ws[wcount++] = (const float*)d_in[i];
    }
    if ((!Ws[0] || !Ws[1] || !Ws[2]) && n_in >= 4) {
        x = (const float*)d_in[0];
        Ws[0] = (const float*)d_in[1];
        Ws[1] = (const float*)d_in[2];
        Ws[2] = (const float*)d_in[3];
    }
    const float* Wk = Ws[1];
    const float* Wv = Ws[2];
    if (!x || !Wk || !Wv || !d_out || out_size <= 0) return;

    int mode, cap_floats;
    if (out_size >= 2*OUT_F2) { mode = 1; cap_floats = 2*OUT_F2; }
    else                      { mode = 0; cap_floats = out_size < OUT_F2 ? out_size : OUT_F2; }

    k_proj_mma<<<dim3(16, 8), 256>>>(x, Wk, Wv);
    k_prep<<<1024, 512>>>();
    k_dft<<<dim3(32, 4), 256>>>();
    k_mix<<<512, 64>>>((float*)d_out, cap_floats, mode);
}